// round 13
// baseline (speedup 1.0000x reference)
#include <cuda_runtime.h>
#include <cuda_bf16.h>
#include <cstdint>

// Problem sizes (fixed by the reference)
#define SEQ_LEN   32768
#define IN_SZ     256
#define HID       512
#define OUT_SZ    256

// Scratch. g_A padded by 2 rows so the 2-deep A prefetch never reads OOB.
__device__ __align__(16) float g_A[(SEQ_LEN + 2) * HID];
__device__ __align__(16) float g_H[SEQ_LEN * HID];

// ---------------------------------------------------------------------------
// No-op kernel: two launched first so ncu's fixed -s 5 -c 1 window lands on
// the scan kernel (validated in R9 — keep).
// ---------------------------------------------------------------------------
__global__ void noop_kernel() {}

// ---------------------------------------------------------------------------
// Generic tiled GEMM: C[M,N] = Am[M,K] @ Bm[N,K]^T + bias[N]   (unchanged)
// ---------------------------------------------------------------------------
__global__ __launch_bounds__(256) void gemm_abt_bias(
    const float* __restrict__ Am, const float* __restrict__ Bm,
    const float* __restrict__ bias, float* __restrict__ C,
    int M, int N, int K)
{
    __shared__ float As[16][65];
    __shared__ float Bs[16][65];

    const int tid = threadIdx.x;
    const int bm = blockIdx.y * 64;
    const int bn = blockIdx.x * 64;
    const int tx = tid & 15;
    const int ty = tid >> 4;
    const int lr = tid >> 2;
    const int lk = (tid & 3) * 4;

    float acc[4][4] = {};

    for (int k0 = 0; k0 < K; k0 += 16) {
        float4 av = *(const float4*)&Am[(size_t)(bm + lr) * K + k0 + lk];
        float4 bv = *(const float4*)&Bm[(size_t)(bn + lr) * K + k0 + lk];
        As[lk + 0][lr] = av.x; As[lk + 1][lr] = av.y;
        As[lk + 2][lr] = av.z; As[lk + 3][lr] = av.w;
        Bs[lk + 0][lr] = bv.x; Bs[lk + 1][lr] = bv.y;
        Bs[lk + 2][lr] = bv.z; Bs[lk + 3][lr] = bv.w;
        __syncthreads();

        #pragma unroll
        for (int kk = 0; kk < 16; kk++) {
            float ar[4], br[4];
            #pragma unroll
            for (int i = 0; i < 4; i++) ar[i] = As[kk][ty * 4 + i];
            #pragma unroll
            for (int i = 0; i < 4; i++) br[i] = Bs[kk][tx * 4 + i];
            #pragma unroll
            for (int i = 0; i < 4; i++)
                #pragma unroll
                for (int jj = 0; jj < 4; jj++)
                    acc[i][jj] = fmaf(ar[i], br[jj], acc[i][jj]);
        }
        __syncthreads();
    }

    float bv[4];
    #pragma unroll
    for (int jj = 0; jj < 4; jj++) bv[jj] = bias[bn + tx * 4 + jj];

    #pragma unroll
    for (int i = 0; i < 4; i++) {
        #pragma unroll
        for (int jj = 0; jj < 4; jj++) {
            C[(size_t)(bm + ty * 4 + i) * N + (bn + tx * 4 + jj)] = acc[i][jj] + bv[jj];
        }
    }
}

// ---------------------------------------------------------------------------
// Scan-kernel helpers
// ---------------------------------------------------------------------------
#define FMA2(acc, a, b) \
    asm("fma.rn.f32x2 %0, %1, %2, %0;" : "+l"(acc) : "l"(a), "l"(b))

__device__ __forceinline__ void mbar_wait(uint32_t mbar, uint32_t parity) {
    asm volatile(
        "{\n\t"
        ".reg .pred P1;\n\t"
        "WAIT_LOOP_%=:\n\t"
        "mbarrier.try_wait.parity.acquire.cta.shared::cta.b64 P1, [%0], %1, 0x989680;\n\t"
        "@P1 bra.uni WAIT_DONE_%=;\n\t"
        "bra.uni WAIT_LOOP_%=;\n\t"
        "WAIT_DONE_%=:\n\t"
        "}"
        :: "r"(mbar), "r"(parity) : "memory");
}

// expect_tx: 8 CTAs x 32 msgs x 8B = 2048 bytes per phase (R9-proven).
__device__ __forceinline__ void mbar_expect_n(uint32_t mbar, uint32_t bytes) {
    asm volatile("mbarrier.arrive.expect_tx.shared.b64 _, [%0], %1;"
                 :: "r"(mbar), "r"(bytes) : "memory");
}

__device__ __forceinline__ uint32_t mapa_rank(uint32_t laddr, uint32_t rnk) {
    uint32_t r;
    asm("mapa.shared::cluster.u32 %0, %1, %2;" : "=r"(r) : "r"(laddr), "r"(rnk));
    return r;
}

// 8-byte remote store completing on the remote CTA's mbarrier.
__device__ __forceinline__ void st_async_b64(uint32_t raddr, unsigned long long v,
                                             uint32_t rmbar) {
    asm volatile(
        "st.async.shared::cluster.mbarrier::complete_tx::bytes.b64 [%0], %1, [%2];"
        :: "r"(raddr), "l"(v), "r"(rmbar) : "memory");
}

// Branchless tanh: 1 - 2/(1 + e^{2x}) via MUFU.EX2 + MUFU.RCP.
__device__ __forceinline__ float fast_tanh(float x) {
    float e;
    asm("ex2.approx.f32 %0, %1;" : "=f"(e) : "f"(x * 2.885390081777927f));
    float r;
    asm("rcp.approx.f32 %0, %1;" : "=f"(r) : "f"(e + 1.0f));
    return fmaf(-2.0f, r, 1.0f);
}

// ---------------------------------------------------------------------------
// Serial recurrence, 8-CTA cluster. R9-proven barrier protocol; NEW compute
// layout cutting SMEM traffic 4x.
//
// Old layout: 512 threads x 64-float reads = 128KB/step from smem -> 1024 cyc
// crossbar floor (the dominant, previously unmodeled cost).
// New layout: warp g owns rows 4g..4g+3; lane c owns k-floats
// {4c+128q .. 4c+128q+4}, q=0..3. Each thread reads 16 floats (4x LDS.128,
// each instruction's lanes covering 512 consecutive bytes -> conflict-free):
// 32KB/step -> 256 cyc floor. FMA2 count (32) and weight regs (64) unchanged.
//
// Reduction: butterfly xor{4,8,16} on the 4 row-accumulators (12 shfl), then
// lane c SELects row (c>>2)&3 and finishes with xor{1,2} (2 shfl): every lane
// holds one complete row of the 4. shfl_xor(4) pairs rows (2p,2p+1); the 16
// lanes with bit2==0 send one b64 to dst CTA (c&3)|((c&16)>>2) — 2 pairs x 8
// dsts per warp, 256 msgs x 8B per CTA per step: byte-identical protocol to
// the R9-passing kernel (single barrier per phase, expect 2048B, all threads
// wait, tid0 re-arms after sends).
// ---------------------------------------------------------------------------
__global__ void __cluster_dims__(8, 1, 1) __launch_bounds__(512, 1)
rnn_scan_kernel(const float* __restrict__ Wh,
                const float* __restrict__ A,
                float* __restrict__ H)
{
    __shared__ __align__(16) float hbuf[2][HID];
    __shared__ __align__(8) unsigned long long mbar[2];

    const int tid = threadIdx.x;
    uint32_t rank;
    asm("mov.u32 %0, %%cluster_ctarank;" : "=r"(rank));

    const int g = tid >> 5;          // warp 0..15: rows 4g..4g+3
    const int c = tid & 31;          // lane
    const int r = (c >> 2) & 3;      // this lane's final row within the group
    const int j0 = (int)rank * 64 + 4 * g;

    // Weights: w2[i][q] = float4 Wh[j0+i][4c+128q .. +4] as 2x f32x2.
    ulonglong2 w2[4][4];
    const ulonglong2* Wh2 = (const ulonglong2*)Wh;   // 128 x 16B per row
    #pragma unroll
    for (int i = 0; i < 4; i++)
        #pragma unroll
        for (int q = 0; q < 4; q++)
            w2[i][q] = Wh2[(size_t)(j0 + i) * 128 + c + 32 * q];

    const ulonglong2* h2_0 = (const ulonglong2*)hbuf[0];
    const ulonglong2* h2_1 = (const ulonglong2*)hbuf[1];

    // h0 = 0 (buffer 1 fully written by remote stores before first read).
    hbuf[0][tid] = 0.0f;

    const uint32_t mb0 = (uint32_t)__cvta_generic_to_shared(&mbar[0]);
    const uint32_t mb1 = (uint32_t)__cvta_generic_to_shared(&mbar[1]);

    if (tid == 0) {
        asm volatile("mbarrier.init.shared.b64 [%0], 1;" :: "r"(mb0) : "memory");
        asm volatile("mbarrier.init.shared.b64 [%0], 1;" :: "r"(mb1) : "memory");
    }
    __syncthreads();
    if (tid == 0) {            // pre-arm phase 0 of both buffers
        mbar_expect_n(mb0, 2048);
        mbar_expect_n(mb1, 2048);
    }

    // Send geometry: sender lanes have bit2==0 (16/warp). dst in 0..7 from
    // bits {0,1,4}; pair (rows 4g+2p, +2p+1) from bit3.
    const bool sender = ((c & 4) == 0);
    const int dst = (c & 3) | ((c & 16) >> 2);
    const int pairbase = ((c >> 3) & 1) * 2;
    const uint32_t r_h0 = mapa_rank(
        (uint32_t)__cvta_generic_to_shared(&hbuf[0][(int)rank * 64 + 4 * g + pairbase]),
        (uint32_t)dst);
    const uint32_t r_h1 = mapa_rank(
        (uint32_t)__cvta_generic_to_shared(&hbuf[1][(int)rank * 64 + 4 * g + pairbase]),
        (uint32_t)dst);
    const uint32_t r_mb0 = mapa_rank(mb0, (uint32_t)dst);
    const uint32_t r_mb1 = mapa_rank(mb1, (uint32_t)dst);
    const bool hstore = ((c & 0x17) == 0);   // lanes 0 and 8: dst==0 senders

    // All CTAs armed and hbuf[0] zeroed before any remote traffic.
    asm volatile("barrier.cluster.arrive.aligned;" ::: "memory");
    asm volatile("barrier.cluster.wait.aligned;"   ::: "memory");

    uint32_t p0 = 0, p1 = 0;

    // 2-deep A prefetch for this lane's row (g_A padded by 2 rows).
    const float* Ap = A + j0 + r;
    float a_cur = Ap[0];
    float a_nxt = Ap[HID];
    Ap += 2 * HID;

    const unsigned mask = 0xffffffffu;

    for (int t = 0; t < SEQ_LEN; t += 2) {
        // ================= even step t: read hbuf[0] -> hbuf[1]/mb1 =================
        if (t > 0) {
            mbar_wait(mb0, p0);
            p0 ^= 1;
        }
        float a_new0 = Ap[0];                 // prefetch A[t+2]

        unsigned long long ac0 = 0ull, ac1 = 0ull, ac2 = 0ull, ac3 = 0ull;
        #pragma unroll
        for (int q = 0; q < 4; q++) {
            ulonglong2 hv = h2_0[c + 32 * q];
            FMA2(ac0, w2[0][q].x, hv.x); FMA2(ac0, w2[0][q].y, hv.y);
            FMA2(ac1, w2[1][q].x, hv.x); FMA2(ac1, w2[1][q].y, hv.y);
            FMA2(ac2, w2[2][q].x, hv.x); FMA2(ac2, w2[2][q].y, hv.y);
            FMA2(ac3, w2[3][q].x, hv.x); FMA2(ac3, w2[3][q].y, hv.y);
        }
        float a0, b0, a1, b1, a2, b2, a3, b3;
        asm("mov.b64 {%0, %1}, %2;" : "=f"(a0), "=f"(b0) : "l"(ac0));
        asm("mov.b64 {%0, %1}, %2;" : "=f"(a1), "=f"(b1) : "l"(ac1));
        asm("mov.b64 {%0, %1}, %2;" : "=f"(a2), "=f"(b2) : "l"(ac2));
        asm("mov.b64 {%0, %1}, %2;" : "=f"(a3), "=f"(b3) : "l"(ac3));
        float s0 = a0 + b0, s1 = a1 + b1, s2 = a2 + b2, s3 = a3 + b3;

        #pragma unroll
        for (int lvl = 4; lvl <= 16; lvl <<= 1) {
            s0 += __shfl_xor_sync(mask, s0, lvl);
            s1 += __shfl_xor_sync(mask, s1, lvl);
            s2 += __shfl_xor_sync(mask, s2, lvl);
            s3 += __shfl_xor_sync(mask, s3, lvl);
        }
        float v = (r & 2) ? ((r & 1) ? s3 : s2) : ((r & 1) ? s1 : s0);
        v += __shfl_xor_sync(mask, v, 1);
        v += __shfl_xor_sync(mask, v, 2);

        float hn = fast_tanh(v + a_cur);

        float other = __shfl_xor_sync(mask, hn, 4);   // partner row r^1
        float lo = (c & 4) ? other : hn;
        float hi = (c & 4) ? hn : other;
        unsigned long long pv;
        asm("mov.b64 %0, {%1, %2};" : "=l"(pv) : "f"(lo), "f"(hi));

        if (sender) {
            st_async_b64(r_h1, pv, r_mb1);
            if (hstore) *(float2*)&H[t * HID + j0 + pairbase] = make_float2(lo, hi);
        }
        if (t > 0 && tid == 0) mbar_expect_n(mb0, 2048);   // re-arm off wake path
        a_cur = a_nxt; a_nxt = a_new0;

        // ================= odd step t+1: read hbuf[1] -> hbuf[0]/mb0 =================
        mbar_wait(mb1, p1);
        p1 ^= 1;
        float a_new1 = Ap[HID];               // prefetch A[t+3]

        ac0 = 0ull; ac1 = 0ull; ac2 = 0ull; ac3 = 0ull;
        #pragma unroll
        for (int q = 0; q < 4; q++) {
            ulonglong2 hv = h2_1[c + 32 * q];
            FMA2(ac0, w2[0][q].x, hv.x); FMA2(ac0, w2[0][q].y, hv.y);
            FMA2(ac1, w2[1][q].x, hv.x); FMA2(ac1, w2[1][q].y, hv.y);
            FMA2(ac2, w2[2][q].x, hv.x); FMA2(ac2, w2[2][q].y, hv.y);
            FMA2(ac3, w2[3][q].x, hv.x); FMA2(ac3, w2[3][q].y, hv.y);
        }
        asm("mov.b64 {%0, %1}, %2;" : "=f"(a0), "=f"(b0) : "l"(ac0));
        asm("mov.b64 {%0, %1}, %2;" : "=f"(a1), "=f"(b1) : "l"(ac1));
        asm("mov.b64 {%0, %1}, %2;" : "=f"(a2), "=f"(b2) : "l"(ac2));
        asm("mov.b64 {%0, %1}, %2;" : "=f"(a3), "=f"(b3) : "l"(ac3));
        s0 = a0 + b0; s1 = a1 + b1; s2 = a2 + b2; s3 = a3 + b3;

        #pragma unroll
        for (int lvl = 4; lvl <= 16; lvl <<= 1) {
            s0 += __shfl_xor_sync(mask, s0, lvl);
            s1 += __shfl_xor_sync(mask, s1, lvl);
            s2 += __shfl_xor_sync(mask, s2, lvl);
            s3 += __shfl_xor_sync(mask, s3, lvl);
        }
        v = (r & 2) ? ((r & 1) ? s3 : s2) : ((r & 1) ? s1 : s0);
        v += __shfl_xor_sync(mask, v, 1);
        v += __shfl_xor_sync(mask, v, 2);

        hn = fast_tanh(v + a_cur);

        other = __shfl_xor_sync(mask, hn, 4);
        lo = (c & 4) ? other : hn;
        hi = (c & 4) ? hn : other;
        asm("mov.b64 %0, {%1, %2};" : "=l"(pv) : "f"(lo), "f"(hi));

        if (sender) {
            if (t + 2 < SEQ_LEN) st_async_b64(r_h0, pv, r_mb0);
            if (hstore) *(float2*)&H[(t + 1) * HID + j0 + pairbase] = make_float2(lo, hi);
        }
        if (tid == 0) mbar_expect_n(mb1, 2048);            // re-arm off wake path
        a_cur = a_nxt; a_nxt = a_new1;

        Ap += 2 * HID;
    }

    // No CTA may exit while peers could still have traffic targeting its smem.
    asm volatile("barrier.cluster.arrive.aligned;" ::: "memory");
    asm volatile("barrier.cluster.wait.aligned;"   ::: "memory");
}

// ---------------------------------------------------------------------------
// Launch: 2x no-op (ncu aiming) -> A-GEMM -> serial scan -> Y-GEMM.
// Graph-capturable, no allocs.
// ---------------------------------------------------------------------------
extern "C" void kernel_launch(void* const* d_in, const int* in_sizes, int n_in,
                              void* d_out, int out_size)
{
    const float* x  = (const float*)d_in[0];   // [32768, 256]
    const float* Wx = (const float*)d_in[1];   // [512, 256]
    const float* Wh = (const float*)d_in[2];   // [512, 512]
    const float* Wy = (const float*)d_in[3];   // [256, 512]
    const float* bh = (const float*)d_in[4];   // [512]
    const float* by = (const float*)d_in[5];   // [256]
    float* y = (float*)d_out;                  // [32768*256]

    float* A;
    float* H;
    cudaGetSymbolAddress((void**)&A, g_A);
    cudaGetSymbolAddress((void**)&H, g_H);

    // Two no-op launches so ncu's fixed -s 5 -c 1 window lands on the scan.
    noop_kernel<<<1, 32>>>();
    noop_kernel<<<1, 32>>>();

    // A = X @ Wx^T + bh : M=SEQ_LEN, N=HID, K=IN_SZ
    gemm_abt_bias<<<dim3(HID / 64, SEQ_LEN / 64), 256>>>(
        x, Wx, bh, A, SEQ_LEN, HID, IN_SZ);

    // Serial scan: 1 cluster of 8 CTAs, 512 threads each.
    rnn_scan_kernel<<<8, 512>>>(Wh, A, H);

    // Y = H @ Wy^T + by : M=SEQ_LEN, N=OUT_SZ, K=HID
    gemm_abt_bias<<<dim3(OUT_SZ / 64, SEQ_LEN / 64), 256>>>(
        H, Wy, by, y, SEQ_LEN, OUT_SZ, HID);
}

// round 15
// speedup vs baseline: 1.4328x; 1.4328x over previous
#include <cuda_runtime.h>
#include <cuda_bf16.h>
#include <cstdint>

// Problem sizes (fixed by the reference)
#define SEQ_LEN   32768
#define IN_SZ     256
#define HID       512
#define OUT_SZ    256

// Scratch. g_A padded by 2 rows so the 2-deep A prefetch never reads OOB.
__device__ __align__(16) float g_A[(SEQ_LEN + 2) * HID];
__device__ __align__(16) float g_H[SEQ_LEN * HID];

// ---------------------------------------------------------------------------
// No-op kernel: two launched first so ncu's fixed -s 5 -c 1 window lands on
// the scan kernel (validated in R9 — keep).
// ---------------------------------------------------------------------------
__global__ void noop_kernel() {}

// ---------------------------------------------------------------------------
// Generic tiled GEMM: C[M,N] = Am[M,K] @ Bm[N,K]^T + bias[N]   (unchanged)
// ---------------------------------------------------------------------------
__global__ __launch_bounds__(256) void gemm_abt_bias(
    const float* __restrict__ Am, const float* __restrict__ Bm,
    const float* __restrict__ bias, float* __restrict__ C,
    int M, int N, int K)
{
    __shared__ float As[16][65];
    __shared__ float Bs[16][65];

    const int tid = threadIdx.x;
    const int bm = blockIdx.y * 64;
    const int bn = blockIdx.x * 64;
    const int tx = tid & 15;
    const int ty = tid >> 4;
    const int lr = tid >> 2;
    const int lk = (tid & 3) * 4;

    float acc[4][4] = {};

    for (int k0 = 0; k0 < K; k0 += 16) {
        float4 av = *(const float4*)&Am[(size_t)(bm + lr) * K + k0 + lk];
        float4 bv = *(const float4*)&Bm[(size_t)(bn + lr) * K + k0 + lk];
        As[lk + 0][lr] = av.x; As[lk + 1][lr] = av.y;
        As[lk + 2][lr] = av.z; As[lk + 3][lr] = av.w;
        Bs[lk + 0][lr] = bv.x; Bs[lk + 1][lr] = bv.y;
        Bs[lk + 2][lr] = bv.z; Bs[lk + 3][lr] = bv.w;
        __syncthreads();

        #pragma unroll
        for (int kk = 0; kk < 16; kk++) {
            float ar[4], br[4];
            #pragma unroll
            for (int i = 0; i < 4; i++) ar[i] = As[kk][ty * 4 + i];
            #pragma unroll
            for (int i = 0; i < 4; i++) br[i] = Bs[kk][tx * 4 + i];
            #pragma unroll
            for (int i = 0; i < 4; i++)
                #pragma unroll
                for (int jj = 0; jj < 4; jj++)
                    acc[i][jj] = fmaf(ar[i], br[jj], acc[i][jj]);
        }
        __syncthreads();
    }

    float bv[4];
    #pragma unroll
    for (int jj = 0; jj < 4; jj++) bv[jj] = bias[bn + tx * 4 + jj];

    #pragma unroll
    for (int i = 0; i < 4; i++) {
        #pragma unroll
        for (int jj = 0; jj < 4; jj++) {
            C[(size_t)(bm + ty * 4 + i) * N + (bn + tx * 4 + jj)] = acc[i][jj] + bv[jj];
        }
    }
}

// ---------------------------------------------------------------------------
// Scan-kernel helpers
// ---------------------------------------------------------------------------
#define FMA2(acc, a, b) \
    asm("fma.rn.f32x2 %0, %1, %2, %0;" : "+l"(acc) : "l"(a), "l"(b))

__device__ __forceinline__ void mbar_wait(uint32_t mbar, uint32_t parity) {
    asm volatile(
        "{\n\t"
        ".reg .pred P1;\n\t"
        "WAIT_LOOP_%=:\n\t"
        "mbarrier.try_wait.parity.acquire.cta.shared::cta.b64 P1, [%0], %1, 0x989680;\n\t"
        "@P1 bra.uni WAIT_DONE_%=;\n\t"
        "bra.uni WAIT_LOOP_%=;\n\t"
        "WAIT_DONE_%=:\n\t"
        "}"
        :: "r"(mbar), "r"(parity) : "memory");
}

// expect_tx: 8 CTAs x 16 packets x 16B = 2048 bytes per phase.
__device__ __forceinline__ void mbar_expect_n(uint32_t mbar, uint32_t bytes) {
    asm volatile("mbarrier.arrive.expect_tx.shared.b64 _, [%0], %1;"
                 :: "r"(mbar), "r"(bytes) : "memory");
}

__device__ __forceinline__ uint32_t mapa_rank(uint32_t laddr, uint32_t rnk) {
    uint32_t r;
    asm("mapa.shared::cluster.u32 %0, %1, %2;" : "=r"(r) : "r"(laddr), "r"(rnk));
    return r;
}

// 16-byte remote store completing on the remote CTA's mbarrier: ONE cluster
// transaction carrying 4 rows (halves per-message port cost vs 2x b64).
__device__ __forceinline__ void st_async_v4(uint32_t raddr,
                                            float v0, float v1, float v2, float v3,
                                            uint32_t rmbar) {
    asm volatile(
        "st.async.shared::cluster.mbarrier::complete_tx::bytes.v4.b32 "
        "[%0], {%1, %2, %3, %4}, [%5];"
        :: "r"(raddr), "f"(v0), "f"(v1), "f"(v2), "f"(v3), "r"(rmbar) : "memory");
}

// Branchless tanh: 1 - 2/(1 + e^{2x}) via MUFU.EX2 + MUFU.RCP.
__device__ __forceinline__ float fast_tanh(float x) {
    float e;
    asm("ex2.approx.f32 %0, %1;" : "=f"(e) : "f"(x * 2.885390081777927f));
    float r;
    asm("rcp.approx.f32 %0, %1;" : "=f"(r) : "f"(e + 1.0f));
    return fmaf(-2.0f, r, 1.0f);
}

// ---------------------------------------------------------------------------
// Serial recurrence, 8-CTA cluster. R13 compute layout (warp g owns rows
// 4g..4g+3; lane c reads h floats {4c+128q}), R9-proven barrier protocol.
// Full 5-level butterfly gives EVERY lane all four finished row sums;
// lanes 0-7 each send one 16-byte st.async.v4 packet to dst CTA = lane.
// 8 sends/warp -> 128 transactions/CTA/step (R13: 256), same 2048B/phase.
// Theory under test: DSMEM cluster-port cost ~4cyc/transaction dominates.
// ---------------------------------------------------------------------------
__global__ void __cluster_dims__(8, 1, 1) __launch_bounds__(512, 1)
rnn_scan_kernel(const float* __restrict__ Wh,
                const float* __restrict__ A,
                float* __restrict__ H)
{
    __shared__ __align__(16) float hbuf[2][HID];
    __shared__ __align__(8) unsigned long long mbar[2];

    const int tid = threadIdx.x;
    uint32_t rank;
    asm("mov.u32 %0, %%cluster_ctarank;" : "=r"(rank));

    const int g = tid >> 5;          // warp 0..15: rows 4g..4g+3
    const int c = tid & 31;          // lane
    const int j0 = (int)rank * 64 + 4 * g;

    // Weights: w2[i][q] = float4 Wh[j0+i][4c+128q .. +4] as 2x f32x2.
    ulonglong2 w2[4][4];
    const ulonglong2* Wh2 = (const ulonglong2*)Wh;   // 128 x 16B per row
    #pragma unroll
    for (int i = 0; i < 4; i++)
        #pragma unroll
        for (int q = 0; q < 4; q++)
            w2[i][q] = Wh2[(size_t)(j0 + i) * 128 + c + 32 * q];

    const ulonglong2* h2_0 = (const ulonglong2*)hbuf[0];
    const ulonglong2* h2_1 = (const ulonglong2*)hbuf[1];

    // h0 = 0 (buffer 1 fully written by remote stores before first read).
    hbuf[0][tid] = 0.0f;

    const uint32_t mb0 = (uint32_t)__cvta_generic_to_shared(&mbar[0]);
    const uint32_t mb1 = (uint32_t)__cvta_generic_to_shared(&mbar[1]);

    if (tid == 0) {
        asm volatile("mbarrier.init.shared.b64 [%0], 1;" :: "r"(mb0) : "memory");
        asm volatile("mbarrier.init.shared.b64 [%0], 1;" :: "r"(mb1) : "memory");
    }
    __syncthreads();
    if (tid == 0) {            // pre-arm phase 0 of both buffers
        mbar_expect_n(mb0, 2048);
        mbar_expect_n(mb1, 2048);
    }

    // Send geometry: lanes 0-7 send this warp's 16B row-quad to dst CTA = c.
    const bool sender = (c < 8);
    const uint32_t slice0 = (uint32_t)__cvta_generic_to_shared(&hbuf[0][(int)rank * 64 + 4 * g]);
    const uint32_t slice1 = (uint32_t)__cvta_generic_to_shared(&hbuf[1][(int)rank * 64 + 4 * g]);
    uint32_t r_h0 = 0, r_h1 = 0, r_mb0 = 0, r_mb1 = 0;
    if (sender) {
        r_h0  = mapa_rank(slice0, (uint32_t)c);
        r_h1  = mapa_rank(slice1, (uint32_t)c);
        r_mb0 = mapa_rank(mb0, (uint32_t)c);
        r_mb1 = mapa_rank(mb1, (uint32_t)c);
    }

    // All CTAs armed and hbuf[0] zeroed before any remote traffic.
    asm volatile("barrier.cluster.arrive.aligned;" ::: "memory");
    asm volatile("barrier.cluster.wait.aligned;"   ::: "memory");

    uint32_t p0 = 0, p1 = 0;

    // 2-deep A prefetch of this warp's row-quad (converged 16B broadcast load;
    // g_A padded by 2 rows).
    const float4* Ap = (const float4*)(A + j0);      // stride HID/4 float4s
    float4 a_cur = Ap[0];
    float4 a_nxt = Ap[HID / 4];
    Ap += 2 * (HID / 4);

    const unsigned mask = 0xffffffffu;

    for (int t = 0; t < SEQ_LEN; t += 2) {
        // ================= even step t: read hbuf[0] -> hbuf[1]/mb1 =================
        if (t > 0) {
            mbar_wait(mb0, p0);
            p0 ^= 1;
        }
        float4 a_new0 = Ap[0];                // prefetch A[t+2]

        unsigned long long ac0 = 0ull, ac1 = 0ull, ac2 = 0ull, ac3 = 0ull;
        #pragma unroll
        for (int q = 0; q < 4; q++) {
            ulonglong2 hv = h2_0[c + 32 * q];
            FMA2(ac0, w2[0][q].x, hv.x); FMA2(ac0, w2[0][q].y, hv.y);
            FMA2(ac1, w2[1][q].x, hv.x); FMA2(ac1, w2[1][q].y, hv.y);
            FMA2(ac2, w2[2][q].x, hv.x); FMA2(ac2, w2[2][q].y, hv.y);
            FMA2(ac3, w2[3][q].x, hv.x); FMA2(ac3, w2[3][q].y, hv.y);
        }
        float a0, b0, a1, b1, a2, b2, a3, b3;
        asm("mov.b64 {%0, %1}, %2;" : "=f"(a0), "=f"(b0) : "l"(ac0));
        asm("mov.b64 {%0, %1}, %2;" : "=f"(a1), "=f"(b1) : "l"(ac1));
        asm("mov.b64 {%0, %1}, %2;" : "=f"(a2), "=f"(b2) : "l"(ac2));
        asm("mov.b64 {%0, %1}, %2;" : "=f"(a3), "=f"(b3) : "l"(ac3));
        float s0 = a0 + b0, s1 = a1 + b1, s2 = a2 + b2, s3 = a3 + b3;

        #pragma unroll
        for (int lvl = 1; lvl <= 16; lvl <<= 1) {    // full butterfly: all lanes
            s0 += __shfl_xor_sync(mask, s0, lvl);    // hold all 4 row sums
            s1 += __shfl_xor_sync(mask, s1, lvl);
            s2 += __shfl_xor_sync(mask, s2, lvl);
            s3 += __shfl_xor_sync(mask, s3, lvl);
        }

        float h0 = fast_tanh(s0 + a_cur.x);
        float h1 = fast_tanh(s1 + a_cur.y);
        float h2v = fast_tanh(s2 + a_cur.z);
        float h3 = fast_tanh(s3 + a_cur.w);

        if (sender) {
            st_async_v4(r_h1, h0, h1, h2v, h3, r_mb1);
            if (c == 0) *(float4*)&H[t * HID + j0] = make_float4(h0, h1, h2v, h3);
        }
        if (t > 0 && tid == 0) mbar_expect_n(mb0, 2048);   // re-arm off wake path
        a_cur = a_nxt; a_nxt = a_new0;

        // ================= odd step t+1: read hbuf[1] -> hbuf[0]/mb0 =================
        mbar_wait(mb1, p1);
        p1 ^= 1;
        float4 a_new1 = Ap[HID / 4];          // prefetch A[t+3]

        ac0 = 0ull; ac1 = 0ull; ac2 = 0ull; ac3 = 0ull;
        #pragma unroll
        for (int q = 0; q < 4; q++) {
            ulonglong2 hv = h2_1[c + 32 * q];
            FMA2(ac0, w2[0][q].x, hv.x); FMA2(ac0, w2[0][q].y, hv.y);
            FMA2(ac1, w2[1][q].x, hv.x); FMA2(ac1, w2[1][q].y, hv.y);
            FMA2(ac2, w2[2][q].x, hv.x); FMA2(ac2, w2[2][q].y, hv.y);
            FMA2(ac3, w2[3][q].x, hv.x); FMA2(ac3, w2[3][q].y, hv.y);
        }
        asm("mov.b64 {%0, %1}, %2;" : "=f"(a0), "=f"(b0) : "l"(ac0));
        asm("mov.b64 {%0, %1}, %2;" : "=f"(a1), "=f"(b1) : "l"(ac1));
        asm("mov.b64 {%0, %1}, %2;" : "=f"(a2), "=f"(b2) : "l"(ac2));
        asm("mov.b64 {%0, %1}, %2;" : "=f"(a3), "=f"(b3) : "l"(ac3));
        s0 = a0 + b0; s1 = a1 + b1; s2 = a2 + b2; s3 = a3 + b3;

        #pragma unroll
        for (int lvl = 1; lvl <= 16; lvl <<= 1) {
            s0 += __shfl_xor_sync(mask, s0, lvl);
            s1 += __shfl_xor_sync(mask, s1, lvl);
            s2 += __shfl_xor_sync(mask, s2, lvl);
            s3 += __shfl_xor_sync(mask, s3, lvl);
        }

        h0 = fast_tanh(s0 + a_cur.x);
        h1 = fast_tanh(s1 + a_cur.y);
        h2v = fast_tanh(s2 + a_cur.z);
        h3 = fast_tanh(s3 + a_cur.w);

        if (sender) {
            if (t + 2 < SEQ_LEN) st_async_v4(r_h0, h0, h1, h2v, h3, r_mb0);
            if (c == 0) *(float4*)&H[(t + 1) * HID + j0] = make_float4(h0, h1, h2v, h3);
        }
        if (tid == 0) mbar_expect_n(mb1, 2048);            // re-arm off wake path
        a_cur = a_nxt; a_nxt = a_new1;

        Ap += 2 * (HID / 4);
    }

    // No CTA may exit while peers could still have traffic targeting its smem.
    asm volatile("barrier.cluster.arrive.aligned;" ::: "memory");
    asm volatile("barrier.cluster.wait.aligned;"   ::: "memory");
}

// ---------------------------------------------------------------------------
// Launch: 2x no-op (ncu aiming) -> A-GEMM -> serial scan -> Y-GEMM.
// Graph-capturable, no allocs.
// ---------------------------------------------------------------------------
extern "C" void kernel_launch(void* const* d_in, const int* in_sizes, int n_in,
                              void* d_out, int out_size)
{
    const float* x  = (const float*)d_in[0];   // [32768, 256]
    const float* Wx = (const float*)d_in[1];   // [512, 256]
    const float* Wh = (const float*)d_in[2];   // [512, 512]
    const float* Wy = (const float*)d_in[3];   // [256, 512]
    const float* bh = (const float*)d_in[4];   // [512]
    const float* by = (const float*)d_in[5];   // [256]
    float* y = (float*)d_out;                  // [32768*256]

    float* A;
    float* H;
    cudaGetSymbolAddress((void**)&A, g_A);
    cudaGetSymbolAddress((void**)&H, g_H);

    // Two no-op launches so ncu's fixed -s 5 -c 1 window lands on the scan.
    noop_kernel<<<1, 32>>>();
    noop_kernel<<<1, 32>>>();

    // A = X @ Wx^T + bh : M=SEQ_LEN, N=HID, K=IN_SZ
    gemm_abt_bias<<<dim3(HID / 64, SEQ_LEN / 64), 256>>>(
        x, Wx, bh, A, SEQ_LEN, HID, IN_SZ);

    // Serial scan: 1 cluster of 8 CTAs, 512 threads each.
    rnn_scan_kernel<<<8, 512>>>(Wh, A, H);

    // Y = H @ Wy^T + by : M=SEQ_LEN, N=OUT_SZ, K=HID
    gemm_abt_bias<<<dim3(OUT_SZ / 64, SEQ_LEN / 64), 256>>>(
        H, Wy, by, y, SEQ_LEN, OUT_SZ, HID);
}